// round 14
// baseline (speedup 1.0000x reference)
#include <cuda_runtime.h>
#include <cstddef>

// ---------------------------------------------------------------------------
// SSIM loss, fused single kernel (v7 = v3 + balanced warp-uniform phase B):
//   Phase B: explicit per-warp task schedule, critical path 1.56H (was 2H).
//   Phase C: horizontal blur + SSIM (byte-identical to best 86.5us kernel).
//   x,y: (48 planes) x 512 x 512 fp32. out[0] = 1 - mean(ssim).
// ---------------------------------------------------------------------------

#define IMG_H 512
#define IMG_W 512

#define TX 128
#define TY 16
#define RX 138          // columns with halo (0..137 used by phase C)
#define RXP 140         // smem row stride (floats), float4-aligned
#define SMEM_V   (TY * RXP)            // 2240 floats per v-blurred array
#define SMEM_BYTES (5 * SMEM_V * 4)    // 44800 B -> 5 blocks/SM

// Gaussian taps, sigma=1.5, window=11 (immediates -> FFMA-imm, rt=1).
#define G0 0.00102838f
#define G1 0.00759874f
#define G2 0.03600077f
#define G3 0.10936069f
#define G4 0.21300553f
#define G5 0.26601172f

__device__ double g_accum;          // zero at load; reset by last block
__device__ unsigned int g_ticket;   // ditto

// 11-tap weighted sum, static indices.
#define TAP11(dst, arr, off)                                   \
    do {                                                       \
        float _s = G0 * (arr)[(off) + 0];                      \
        _s = fmaf(G1, (arr)[(off) + 1], _s);                   \
        _s = fmaf(G2, (arr)[(off) + 2], _s);                   \
        _s = fmaf(G3, (arr)[(off) + 3], _s);                   \
        _s = fmaf(G4, (arr)[(off) + 4], _s);                   \
        _s = fmaf(G5, (arr)[(off) + 5], _s);                   \
        _s = fmaf(G4, (arr)[(off) + 6], _s);                   \
        _s = fmaf(G3, (arr)[(off) + 7], _s);                   \
        _s = fmaf(G2, (arr)[(off) + 8], _s);                   \
        _s = fmaf(G1, (arr)[(off) + 9], _s);                   \
        _s = fmaf(G0, (arr)[(off) + 10], _s);                  \
        (dst) = _s;                                            \
    } while (0)

// Vertical blur of one column: blur(src) and blur(src^2).
// NR = window rows, NO = output rows. vl/vs already offset by column.
template <int NR, int NO>
__device__ __forceinline__ void vblur_linsq(const float* __restrict__ src,
                                            float* __restrict__ vl,
                                            float* __restrict__ vs,
                                            int gc, int grow0, int orow0) {
    const bool inw = (unsigned)gc < IMG_W;
    float a[NR];
#pragma unroll
    for (int r = 0; r < NR; ++r) {
        int gr = grow0 + r;
        a[r] = (inw && (unsigned)gr < IMG_H) ? __ldg(src + gr * IMG_W + gc) : 0.0f;
    }
#pragma unroll
    for (int o = 0; o < NO; ++o) { float s; TAP11(s, a, o); vl[(orow0 + o) * RXP] = s; }
#pragma unroll
    for (int r = 0; r < NR; ++r) a[r] *= a[r];
#pragma unroll
    for (int o = 0; o < NO; ++o) { float s; TAP11(s, a, o); vs[(orow0 + o) * RXP] = s; }
}

// Vertical blur of the xy product column.
template <int NR, int NO>
__device__ __forceinline__ void vblur_xy(const float* __restrict__ xs,
                                         const float* __restrict__ ys,
                                         float* __restrict__ v4,
                                         int gc, int grow0, int orow0) {
    const bool inw = (unsigned)gc < IMG_W;
    float a[NR];
#pragma unroll
    for (int r = 0; r < NR; ++r) {
        int gr = grow0 + r;
        bool ok = inw && ((unsigned)gr < IMG_H);
        float xv = ok ? __ldg(xs + gr * IMG_W + gc) : 0.0f;
        float yv = ok ? __ldg(ys + gr * IMG_W + gc) : 0.0f;
        a[r] = xv * yv;
    }
#pragma unroll
    for (int o = 0; o < NO; ++o) { float s; TAP11(s, a, o); v4[(orow0 + o) * RXP] = s; }
}

__global__ void __launch_bounds__(256, 5)
ssim_fused_kernel(const float* __restrict__ x, const float* __restrict__ y,
                  float* __restrict__ out, float inv_n) {
    extern __shared__ float sm[];
    float* __restrict__ vp = sm;   // [5][TY][RXP]: mux, muy, xx, yy, xy

    const int tid   = threadIdx.x;
    const int wid   = tid >> 5;
    const int lane  = tid & 31;
    const int plane = blockIdx.z;
    const int row0  = (int)blockIdx.y * TY - 5;
    const int col0  = (int)blockIdx.x * TX - 5;

    const float* __restrict__ xb = x + (size_t)plane * (IMG_H * IMG_W);
    const float* __restrict__ yb = y + (size_t)plane * (IMG_H * IMG_W);

    // ---- Phase B: vertical blur, balanced warp-uniform schedule -----------
    // Heavy H = full 26-row lin+sq column; light L = xy column (~0.55H);
    // half = 18-row lin+sq (~0.55H). Per-warp totals <= 1.56H (v3 was 2H).
    //   slot 1: w0-3: x cols 0..127 | w4-6: y cols 0..95 | w7: x/y tails 128..137
    //   slot 2: w0-3: xy cols 0..127 | w4: xy tail | w5: y 96..127 top half
    //           w6: y 96..127 bottom half | w7: idle
    // ---- slot 1 ----
    if (wid < 4) {
        int c = wid * 32 + lane;
        vblur_linsq<26, 16>(xb, vp + 0 * SMEM_V + c, vp + 2 * SMEM_V + c,
                            col0 + c, row0, 0);
    } else if (wid < 7) {
        int c = (wid - 4) * 32 + lane;
        vblur_linsq<26, 16>(yb, vp + 1 * SMEM_V + c, vp + 3 * SMEM_V + c,
                            col0 + c, row0, 0);
    } else if (lane < 20) {                       // w7: lin tails
        int isy = lane >= 10;
        int c = 128 + (isy ? lane - 10 : lane);   // cols 128..137
        const float* src = isy ? yb : xb;
        float* vl = vp + (isy ? 1 : 0) * SMEM_V + c;
        float* vs = vp + (isy ? 3 : 2) * SMEM_V + c;
        vblur_linsq<26, 16>(src, vl, vs, col0 + c, row0, 0);
    }
    // ---- slot 2 ----
    if (wid < 4) {
        int c = wid * 32 + lane;
        vblur_xy<26, 16>(xb, yb, vp + 4 * SMEM_V + c, col0 + c, row0, 0);
    } else if (wid == 4) {
        if (lane < 10) {
            int c = 128 + lane;                   // xy tail cols 128..137
            vblur_xy<26, 16>(xb, yb, vp + 4 * SMEM_V + c, col0 + c, row0, 0);
        }
    } else if (wid == 5) {
        int c = 96 + lane;                        // y cols 96..127, rows 0..7
        vblur_linsq<18, 8>(yb, vp + 1 * SMEM_V + c, vp + 3 * SMEM_V + c,
                           col0 + c, row0, 0);
    } else if (wid == 6) {
        int c = 96 + lane;                        // y cols 96..127, rows 8..15
        vblur_linsq<18, 8>(yb, vp + 1 * SMEM_V + c, vp + 3 * SMEM_V + c,
                           col0 + c, row0 + 8, 8);
    }
    __syncthreads();

    // ---- Phase C: horizontal blur + SSIM (identical to 86.5us version) ----
    const float C1 = 1e-4f;   // (0.01*1)^2
    const float C2 = 9e-4f;   // (0.03*1)^2
    float lsum = 0.0f;

#pragma unroll
    for (int it = 0; it < 2; ++it) {
        int T   = it * 256 + tid;
        int row = T >> 5;
        int c0  = (T & 31) << 2;

        float res[5][4];
#pragma unroll
        for (int q = 0; q < 5; ++q) {
            const float* __restrict__ base = vp + q * SMEM_V + row * RXP + c0;
            float w[16];
#pragma unroll
            for (int k = 0; k < 4; ++k) {
                float4 t4 = *reinterpret_cast<const float4*>(base + 4 * k);
                w[4 * k + 0] = t4.x;
                w[4 * k + 1] = t4.y;
                w[4 * k + 2] = t4.z;
                w[4 * k + 3] = t4.w;
            }
#pragma unroll
            for (int j = 0; j < 4; ++j) TAP11(res[q][j], w, j);
        }

#pragma unroll
        for (int j = 0; j < 4; ++j) {
            float mux  = res[0][j];
            float muy  = res[1][j];
            float mux2 = mux * mux;
            float muy2 = muy * muy;
            float muxy = mux * muy;
            float sx_  = res[2][j] - mux2;
            float sy_  = res[3][j] - muy2;
            float sxy_ = res[4][j] - muxy;
            float num = (2.0f * muxy + C1) * (2.0f * sxy_ + C2);
            float den = (mux2 + muy2 + C1) * (sx_ + sy_ + C2) + 1e-8f;
            lsum += __fdividef(num, den);
        }
    }

    // ---- Block reduce + global accumulate + last-block finalize -----------
#pragma unroll
    for (int o = 16; o; o >>= 1)
        lsum += __shfl_xor_sync(0xffffffffu, lsum, o);

    __shared__ float wsum[8];
    if (lane == 0) wsum[wid] = lsum;
    __syncthreads();
    if (tid == 0) {
        float t = 0.0f;
#pragma unroll
        for (int i = 0; i < 8; ++i) t += wsum[i];
        atomicAdd(&g_accum, (double)t);
        __threadfence();
        unsigned int nb = gridDim.x * gridDim.y * gridDim.z;
        unsigned int tk = atomicAdd(&g_ticket, 1u);
        if (tk == nb - 1u) {
            double total = atomicAdd(&g_accum, 0.0);   // coherent L2 read
            out[0] = 1.0f - (float)(total * (double)inv_n);
            g_accum  = 0.0;     // reset for next graph replay
            g_ticket = 0u;
        }
    }
}

extern "C" void kernel_launch(void* const* d_in, const int* in_sizes, int n_in,
                              void* d_out, int out_size) {
    const float* x = (const float*)d_in[0];
    const float* y = (const float*)d_in[1];
    float* out = (float*)d_out;

    const int planes = in_sizes[0] / (IMG_H * IMG_W);   // 48
    const float inv_n = 1.0f / (float)in_sizes[0];

    dim3 grid(IMG_W / TX, IMG_H / TY, planes);   // 4 x 32 x 48 = 6144 blocks
    ssim_fused_kernel<<<grid, 256, SMEM_BYTES>>>(x, y, out, inv_n);
}

// round 15
// speedup vs baseline: 1.0010x; 1.0010x over previous
#include <cuda_runtime.h>
#include <cstddef>

// ---------------------------------------------------------------------------
// SSIM loss, fused single kernel (v9 = v3 structure, TY=8, streamed phase C):
//   Phase B: v3's looped vertical blur (global->regs->smem), 18-row window.
//   Phase C: horizontal blur with A/B/S streaming partials (low regs).
//   6 blocks/SM (regs 42, smem 22.4KB). x,y: 48 x 512 x 512 fp32.
// ---------------------------------------------------------------------------

#define IMG_H 512
#define IMG_W 512

#define TX 128
#define TY 8
#define RX 138          // TX + 10 columns needed (with halo)
#define RY 18           // TY + 10 rows
#define RXP 140         // padded row stride (floats), float4-aligned
#define SMEM_V   (TY * RXP)            // 1120 floats per v-blurred array
#define SMEM_BYTES (5 * SMEM_V * 4)    // 22400 B

// Warp-aligned group stride for vertical-blur tasks (RX=138 -> pad to 160).
#define GSTRIDE 160

// Gaussian taps, sigma=1.5, window=11 (immediates -> FFMA-imm, rt=1).
#define G0 0.00102838f
#define G1 0.00759874f
#define G2 0.03600077f
#define G3 0.10936069f
#define G4 0.21300553f
#define G5 0.26601172f

__device__ double g_accum;          // zero at load; reset by last block
__device__ unsigned int g_ticket;   // ditto

// 11-tap weighted sum, static indices.
#define TAP11(dst, arr, off)                                   \
    do {                                                       \
        float _s = G0 * (arr)[(off) + 0];                      \
        _s = fmaf(G1, (arr)[(off) + 1], _s);                   \
        _s = fmaf(G2, (arr)[(off) + 2], _s);                   \
        _s = fmaf(G3, (arr)[(off) + 3], _s);                   \
        _s = fmaf(G4, (arr)[(off) + 4], _s);                   \
        _s = fmaf(G5, (arr)[(off) + 5], _s);                   \
        _s = fmaf(G4, (arr)[(off) + 6], _s);                   \
        _s = fmaf(G3, (arr)[(off) + 7], _s);                   \
        _s = fmaf(G2, (arr)[(off) + 8], _s);                   \
        _s = fmaf(G1, (arr)[(off) + 9], _s);                   \
        _s = fmaf(G0, (arr)[(off) + 10], _s);                  \
        (dst) = _s;                                            \
    } while (0)

// Load a 16-float window for (q, row, c0) and produce 4 horizontal taps.
#define HLOAD_TAPS(q, dstv)                                           \
    do {                                                              \
        const float* __restrict__ _b = vp + (q) * SMEM_V + row * RXP + c0; \
        float _w[16];                                                 \
        _Pragma("unroll")                                             \
        for (int _k = 0; _k < 4; ++_k) {                              \
            float4 _t4 = *reinterpret_cast<const float4*>(_b + 4 * _k); \
            _w[4 * _k + 0] = _t4.x;                                   \
            _w[4 * _k + 1] = _t4.y;                                   \
            _w[4 * _k + 2] = _t4.z;                                   \
            _w[4 * _k + 3] = _t4.w;                                   \
        }                                                             \
        _Pragma("unroll")                                             \
        for (int _j = 0; _j < 4; ++_j) TAP11((dstv)[_j], _w, _j);     \
    } while (0)

__global__ void __launch_bounds__(256, 6)
ssim_fused_kernel(const float* __restrict__ x, const float* __restrict__ y,
                  float* __restrict__ out, float inv_n) {
    extern __shared__ float sm[];
    float* __restrict__ vp = sm;   // [5][TY][RXP]: mux, muy, xx, yy, xy

    const int tid   = threadIdx.x;
    const int plane = blockIdx.z;
    const int row0  = (int)blockIdx.y * TY - 5;
    const int col0  = (int)blockIdx.x * TX - 5;

    const float* __restrict__ xb = x + (size_t)plane * (IMG_H * IMG_W);
    const float* __restrict__ yb = y + (size_t)plane * (IMG_H * IMG_W);

    // ---- Phase B: vertical blur, global -> registers -> smem (v3 shape) ---
    //   group 0: x  -> mux (v0), xx (v2)
    //   group 1: y  -> muy (v1), yy (v3)
    //   group 2: xy -> xy  (v4)
    for (int task = tid; task < 3 * GSTRIDE; task += 256) {
        const int g   = task / GSTRIDE;
        const int col = task - g * GSTRIDE;
        if (col >= RX) continue;
        const int gc = col0 + col;
        const bool inw = (unsigned)gc < IMG_W;

        float a[RY];
        if (g == 2) {
#pragma unroll
            for (int r = 0; r < RY; ++r) {
                int gr = row0 + r;
                bool ok = inw && ((unsigned)gr < IMG_H);
                float xv = ok ? __ldg(xb + gr * IMG_W + gc) : 0.0f;
                float yv = ok ? __ldg(yb + gr * IMG_W + gc) : 0.0f;
                a[r] = xv * yv;
            }
            float* __restrict__ v4 = vp + 4 * SMEM_V + col;
#pragma unroll
            for (int r = 0; r < TY; ++r) { float s; TAP11(s, a, r); v4[r * RXP] = s; }
        } else {
            const float* __restrict__ src = g ? yb : xb;
#pragma unroll
            for (int r = 0; r < RY; ++r) {
                int gr = row0 + r;
                bool ok = inw && ((unsigned)gr < IMG_H);
                a[r] = ok ? __ldg(src + gr * IMG_W + gc) : 0.0f;
            }
            float* __restrict__ vl = vp + g * SMEM_V + col;
#pragma unroll
            for (int r = 0; r < TY; ++r) { float s; TAP11(s, a, r); vl[r * RXP] = s; }
#pragma unroll
            for (int r = 0; r < RY; ++r) a[r] *= a[r];
            float* __restrict__ vs = vp + (2 + g) * SMEM_V + col;
#pragma unroll
            for (int r = 0; r < TY; ++r) { float s; TAP11(s, a, r); vs[r * RXP] = s; }
        }
    }
    __syncthreads();

    // ---- Phase C: horizontal blur + SSIM, streamed partials ---------------
    // Exactly one task per thread: row = tid>>5 (0..7), c0 = (tid&31)*4.
    // A = mux^2+muy^2+C1 ; B = 2*mux*muy+C1 ; S = xx+yy ; then xy -> SSIM:
    //   num = B * (2*xy - B + C1 + C2)
    //   den = A * (S  - A + C1 + C2) + 1e-8
    const float C1 = 1e-4f;   // (0.01*1)^2
    const float C2 = 9e-4f;   // (0.03*1)^2
    const int row = tid >> 5;
    const int c0  = (tid & 31) << 2;

    float lsum = 0.0f;
    {
        float mux[4], muy[4], A[4], B[4], S[4], t[4];
        HLOAD_TAPS(0, mux);
        HLOAD_TAPS(1, muy);
#pragma unroll
        for (int j = 0; j < 4; ++j) {
            A[j] = fmaf(mux[j], mux[j], fmaf(muy[j], muy[j], C1));
            B[j] = fmaf(2.0f * mux[j], muy[j], C1);
        }
        HLOAD_TAPS(2, S);
        HLOAD_TAPS(3, t);
#pragma unroll
        for (int j = 0; j < 4; ++j) S[j] += t[j];
        HLOAD_TAPS(4, t);                      // t = blur(xy)
#pragma unroll
        for (int j = 0; j < 4; ++j) {
            float num = B[j] * (2.0f * t[j] - B[j] + (C1 + C2));
            float den = fmaf(A[j], (S[j] - A[j] + (C1 + C2)), 1e-8f);
            lsum += __fdividef(num, den);
        }
    }

    // ---- Block reduce + global accumulate + last-block finalize -----------
#pragma unroll
    for (int o = 16; o; o >>= 1)
        lsum += __shfl_xor_sync(0xffffffffu, lsum, o);

    __shared__ float wsum[8];
    if ((tid & 31) == 0) wsum[tid >> 5] = lsum;
    __syncthreads();
    if (tid == 0) {
        float t = 0.0f;
#pragma unroll
        for (int i = 0; i < 8; ++i) t += wsum[i];
        atomicAdd(&g_accum, (double)t);
        __threadfence();
        unsigned int nb = gridDim.x * gridDim.y * gridDim.z;
        unsigned int tk = atomicAdd(&g_ticket, 1u);
        if (tk == nb - 1u) {
            double total = atomicAdd(&g_accum, 0.0);   // coherent L2 read
            out[0] = 1.0f - (float)(total * (double)inv_n);
            g_accum  = 0.0;     // reset for next graph replay
            g_ticket = 0u;
        }
    }
}

extern "C" void kernel_launch(void* const* d_in, const int* in_sizes, int n_in,
                              void* d_out, int out_size) {
    const float* x = (const float*)d_in[0];
    const float* y = (const float*)d_in[1];
    float* out = (float*)d_out;

    const int planes = in_sizes[0] / (IMG_H * IMG_W);   // 48
    const float inv_n = 1.0f / (float)in_sizes[0];

    dim3 grid(IMG_W / TX, IMG_H / TY, planes);   // 4 x 64 x 48 = 12288 blocks
    ssim_fused_kernel<<<grid, 256, SMEM_BYTES>>>(x, y, out, inv_n);
}

// round 16
// speedup vs baseline: 1.1436x; 1.1424x over previous
#include <cuda_runtime.h>
#include <cstddef>

// ---------------------------------------------------------------------------
// SSIM loss, fused single kernel (v10 = v3 + balanced 2-round phase B +
// streamed phase C). TY=16 tile (best halo economy), 256 thr, 5 blocks/SM.
// x,y: (48 planes) x 512 x 512 fp32. out[0] = 1 - mean(ssim).
// ---------------------------------------------------------------------------

#define IMG_H 512
#define IMG_W 512

#define TX 128
#define TY 16
#define RX 138          // columns with halo
#define RY 26           // rows with halo
#define RXP 140         // smem row stride (floats), float4-aligned
#define SMEM_V   (TY * RXP)            // 2240 floats per v-array
#define SMEM_BYTES (5 * SMEM_V * 4)    // 44800 B -> 5 blocks/SM

// Gaussian taps, sigma=1.5, window=11 (immediates -> FFMA-imm, rt=1).
#define G0 0.00102838f
#define G1 0.00759874f
#define G2 0.03600077f
#define G3 0.10936069f
#define G4 0.21300553f
#define G5 0.26601172f

__device__ double g_accum;          // zero at load; reset by last block
__device__ unsigned int g_ticket;   // ditto

#define TAP11(dst, arr, off)                                   \
    do {                                                       \
        float _s = G0 * (arr)[(off) + 0];                      \
        _s = fmaf(G1, (arr)[(off) + 1], _s);                   \
        _s = fmaf(G2, (arr)[(off) + 2], _s);                   \
        _s = fmaf(G3, (arr)[(off) + 3], _s);                   \
        _s = fmaf(G4, (arr)[(off) + 4], _s);                   \
        _s = fmaf(G5, (arr)[(off) + 5], _s);                   \
        _s = fmaf(G4, (arr)[(off) + 6], _s);                   \
        _s = fmaf(G3, (arr)[(off) + 7], _s);                   \
        _s = fmaf(G2, (arr)[(off) + 8], _s);                   \
        _s = fmaf(G1, (arr)[(off) + 9], _s);                   \
        _s = fmaf(G0, (arr)[(off) + 10], _s);                  \
        (dst) = _s;                                            \
    } while (0)

// Load 16-float smem window for (q,row,c0), produce 4 horizontal taps.
#define HLOAD_TAPS(q, dstv)                                               \
    do {                                                                  \
        const float* __restrict__ _b = vp + (q) * SMEM_V + row * RXP + c0;\
        float _w[16];                                                     \
        _Pragma("unroll")                                                 \
        for (int _k = 0; _k < 4; ++_k) {                                  \
            float4 _t4 = *reinterpret_cast<const float4*>(_b + 4 * _k);   \
            _w[4 * _k + 0] = _t4.x;                                       \
            _w[4 * _k + 1] = _t4.y;                                       \
            _w[4 * _k + 2] = _t4.z;                                       \
            _w[4 * _k + 3] = _t4.w;                                       \
        }                                                                 \
        _Pragma("unroll")                                                 \
        for (int _j = 0; _j < 4; ++_j) TAP11((dstv)[_j], _w, _j);         \
    } while (0)

__global__ void __launch_bounds__(256, 5)
ssim_fused_kernel(const float* __restrict__ x, const float* __restrict__ y,
                  float* __restrict__ out, float inv_n) {
    extern __shared__ float sm[];
    float* __restrict__ vp = sm;   // [5][TY][RXP]: mux, muy, xx, yy, xy

    const int tid   = threadIdx.x;
    const int plane = blockIdx.z;
    const int row0  = (int)blockIdx.y * TY - 5;
    const int col0  = (int)blockIdx.x * TX - 5;

    const float* __restrict__ xb = x + (size_t)plane * (IMG_H * IMG_W);
    const float* __restrict__ yb = y + (size_t)plane * (IMG_H * IMG_W);

    // ---- Phase B round 1: 256 full heavy lin+sq tasks (uniform body) ------
    // tid 0..137 -> x cols 0..137 ; tid 138..255 -> y cols 0..117.
    {
        const int  isy = tid >= 138;
        const int  col = isy ? tid - 138 : tid;
        const float* __restrict__ src = isy ? yb : xb;
        float* __restrict__ vl = vp + (isy ? 1 : 0) * SMEM_V + col;
        float* __restrict__ vs = vp + (isy ? 3 : 2) * SMEM_V + col;
        const int  gc  = col0 + col;
        const bool inw = (unsigned)gc < IMG_W;

        float a[RY];
#pragma unroll
        for (int r = 0; r < RY; ++r) {
            int gr = row0 + r;
            a[r] = (inw && (unsigned)gr < IMG_H) ? __ldg(src + gr * IMG_W + gc)
                                                 : 0.0f;
        }
#pragma unroll
        for (int o = 0; o < TY; ++o) { float s; TAP11(s, a, o); vl[o * RXP] = s; }
#pragma unroll
        for (int r = 0; r < RY; ++r) a[r] *= a[r];
#pragma unroll
        for (int o = 0; o < TY; ++o) { float s; TAP11(s, a, o); vs[o * RXP] = s; }
    }

    // ---- Phase B round 2: light tasks, warp-aligned -----------------------
    // warps 0-4 (tid<160): xy cols 0..137 (lanes with tid<138).
    // warps 5-6 (tid 160..199): y cols 118..137 split in 2 half-windows.
    if (tid < 160) {
        if (tid < 138) {
            const int  col = tid;
            const int  gc  = col0 + col;
            const bool inw = (unsigned)gc < IMG_W;
            float a[RY];
#pragma unroll
            for (int r = 0; r < RY; ++r) {
                int gr = row0 + r;
                bool ok = inw && ((unsigned)gr < IMG_H);
                float xv = ok ? __ldg(xb + gr * IMG_W + gc) : 0.0f;
                float yv = ok ? __ldg(yb + gr * IMG_W + gc) : 0.0f;
                a[r] = xv * yv;
            }
            float* __restrict__ v4 = vp + 4 * SMEM_V + col;
#pragma unroll
            for (int o = 0; o < TY; ++o) { float s; TAP11(s, a, o); v4[o * RXP] = s; }
        }
    } else if (tid < 200) {
        const int idx  = tid - 160;        // 0..39
        const int col  = 118 + (idx % 20); // y cols 118..137
        const int half = idx / 20;         // 0: rows 0..7, 1: rows 8..15
        const int gr0  = row0 + half * 8;
        const int ob   = half * 8;
        const int gc   = col0 + col;
        const bool inw = (unsigned)gc < IMG_W;

        float a[18];
#pragma unroll
        for (int r = 0; r < 18; ++r) {
            int gr = gr0 + r;
            a[r] = (inw && (unsigned)gr < IMG_H) ? __ldg(yb + gr * IMG_W + gc)
                                                 : 0.0f;
        }
        float* __restrict__ vl = vp + 1 * SMEM_V + col;
        float* __restrict__ vs = vp + 3 * SMEM_V + col;
#pragma unroll
        for (int o = 0; o < 8; ++o) { float s; TAP11(s, a, o); vl[(ob + o) * RXP] = s; }
#pragma unroll
        for (int r = 0; r < 18; ++r) a[r] *= a[r];
#pragma unroll
        for (int o = 0; o < 8; ++o) { float s; TAP11(s, a, o); vs[(ob + o) * RXP] = s; }
    }
    __syncthreads();

    // ---- Phase C: horizontal blur + SSIM, streamed A/B/S partials ---------
    //   A = mux^2+muy^2+C1 ; B = 2*mux*muy+C1 ; S = xx+yy
    //   num = B*(2*xy - B + C1+C2) ; den = A*(S - A + C1+C2) + 1e-8
    const float C1 = 1e-4f;
    const float C2 = 9e-4f;
    float lsum = 0.0f;

#pragma unroll
    for (int it = 0; it < 2; ++it) {
        const int T   = it * 256 + tid;
        const int row = T >> 5;
        const int c0  = (T & 31) << 2;

        float mux[4], muy[4], A[4], B[4], S[4], t[4];
        HLOAD_TAPS(0, mux);
        HLOAD_TAPS(1, muy);
#pragma unroll
        for (int j = 0; j < 4; ++j) {
            A[j] = fmaf(mux[j], mux[j], fmaf(muy[j], muy[j], C1));
            B[j] = fmaf(2.0f * mux[j], muy[j], C1);
        }
        HLOAD_TAPS(2, S);
        HLOAD_TAPS(3, t);
#pragma unroll
        for (int j = 0; j < 4; ++j) S[j] += t[j];
        HLOAD_TAPS(4, t);                  // t = blur(xy)
#pragma unroll
        for (int j = 0; j < 4; ++j) {
            float num = B[j] * (2.0f * t[j] - B[j] + (C1 + C2));
            float den = fmaf(A[j], (S[j] - A[j] + (C1 + C2)), 1e-8f);
            lsum += __fdividef(num, den);
        }
    }

    // ---- Block reduce + global accumulate + last-block finalize -----------
#pragma unroll
    for (int o = 16; o; o >>= 1)
        lsum += __shfl_xor_sync(0xffffffffu, lsum, o);

    __shared__ float wsum[8];
    if ((tid & 31) == 0) wsum[tid >> 5] = lsum;
    __syncthreads();
    if (tid == 0) {
        float t = 0.0f;
#pragma unroll
        for (int i = 0; i < 8; ++i) t += wsum[i];
        atomicAdd(&g_accum, (double)t);
        __threadfence();
        unsigned int nb = gridDim.x * gridDim.y * gridDim.z;
        unsigned int tk = atomicAdd(&g_ticket, 1u);
        if (tk == nb - 1u) {
            double total = atomicAdd(&g_accum, 0.0);   // coherent L2 read
            out[0] = 1.0f - (float)(total * (double)inv_n);
            g_accum  = 0.0;     // reset for next graph replay
            g_ticket = 0u;
        }
    }
}

extern "C" void kernel_launch(void* const* d_in, const int* in_sizes, int n_in,
                              void* d_out, int out_size) {
    const float* x = (const float*)d_in[0];
    const float* y = (const float*)d_in[1];
    float* out = (float*)d_out;

    const int planes = in_sizes[0] / (IMG_H * IMG_W);   // 48
    const float inv_n = 1.0f / (float)in_sizes[0];

    dim3 grid(IMG_W / TX, IMG_H / TY, planes);   // 4 x 32 x 48 = 6144 blocks
    ssim_fused_kernel<<<grid, 256, SMEM_BYTES>>>(x, y, out, inv_n);
}